// round 4
// baseline (speedup 1.0000x reference)
#include <cuda_runtime.h>
#include <cuda_bf16.h>
#include <cstdint>

#define NV_V    100001
#define NV_VPAD 100096
#define NB      1024
#define NL      200
#define ND      64
#define NCH     1563          // ceil(100001/64); coverage 100032
#define PAD_N   31.0f         // 100032 - 100001 zero-padded cols, each contributes 2^0 = 1
#define GX      74

// ---------------- device-global scratch (no allocs allowed) ----------------
__device__ __nv_bfloat16 g_E[(size_t)NV_VPAD * ND];   // bf16 item_emb; tail rows stay zero
__device__ __nv_bfloat16 g_Q[NB * ND];                // bf16 Q, pre-scaled by log2(e)
__device__ float g_Spart[GX][NB];                     // per-x-CTA partial softmax denominators
__device__ float g_LP[NB];                            // logit at pred[b] (fp32)

__device__ __forceinline__ uint32_t smem_u32(const void* p) {
    uint32_t a;
    asm("{ .reg .u64 t; cvta.to.shared.u64 t, %1; cvt.u32.u64 %0, t; }" : "=r"(a) : "l"(p));
    return a;
}
__device__ __forceinline__ float ex2f(float x) {
    float r; asm("ex2.approx.ftz.f32 %0, %1;" : "=f"(r) : "f"(x)); return r;
}
__device__ __forceinline__ void cp_async16(uint32_t dst, const void* src) {
    asm volatile("cp.async.cg.shared.global [%0], [%1], 16;" :: "r"(dst), "l"(src) : "memory");
}

// ---------------- K0: fp32 -> bf16 item_emb table ----------------
__global__ __launch_bounds__(256) void convert_kernel(const float* __restrict__ emb) {
    int i = blockIdx.x * 256 + threadIdx.x;
    const int n = NV_V * ND / 2;
    if (i < n) {
        float2 v = reinterpret_cast<const float2*>(emb)[i];
        reinterpret_cast<__nv_bfloat162*>(g_E)[i] = __floats2bfloat162_rn(v.x, v.y);
    }
}

// ---------------- K1: attention pooling -> Q (bf16, *log2e) and lp[b] ----------------
__global__ __launch_bounds__(256) void q_kernel(const int* __restrict__ log_seqs,
                                                const int* __restrict__ pred,
                                                const float* __restrict__ item_emb,
                                                const float* __restrict__ attn_key,
                                                const float* __restrict__ pos_emb) {
    __shared__ __nv_bfloat16 sseq[NL][ND];
    __shared__ float ssim[NL];
    __shared__ float skey[ND];
    __shared__ float sred[8];
    __shared__ float sq[4][ND];

    const int b = blockIdx.x;
    const int t = threadIdx.x, w = t >> 5, lane = t & 31;
    if (t < ND) skey[t] = attn_key[t];
    __syncthreads();

    // pass 1: gather + build seqs (bf16 in smem), sim = seqs . key
    for (int l = w; l < NL; l += 8) {
        int id = log_seqs[b * NL + l];
        int d0 = lane * 2;
        float2 e = *reinterpret_cast<const float2*>(item_emb + (size_t)id * ND + d0);
        float2 p = *reinterpret_cast<const float2*>(pos_emb + l * ND + d0);
        float v0 = 0.f, v1 = 0.f;
        if (id != 0) { v0 = e.x * 8.f + p.x; v1 = e.y * 8.f + p.y; }
        sseq[l][d0]     = __float2bfloat16(v0);
        sseq[l][d0 + 1] = __float2bfloat16(v1);
        float s = v0 * skey[d0] + v1 * skey[d0 + 1];
        #pragma unroll
        for (int o = 16; o > 0; o >>= 1) s += __shfl_xor_sync(0xFFFFFFFFu, s, o);
        if (lane == 0) ssim[l] = (id != 0) ? s : -1e30f;
    }
    __syncthreads();

    // softmax over L
    float v = (t < NL) ? ssim[t] : -1e30f;
    float m = v;
    #pragma unroll
    for (int o = 16; o > 0; o >>= 1) m = fmaxf(m, __shfl_xor_sync(0xFFFFFFFFu, m, o));
    if (lane == 0) sred[w] = m;
    __syncthreads();
    if (t == 0) { float mm = sred[0]; for (int i = 1; i < 8; i++) mm = fmaxf(mm, sred[i]); sred[0] = mm; }
    __syncthreads();
    const float mx = sred[0];
    __syncthreads();
    float e = (t < NL) ? __expf(v - mx) : 0.f;
    if (t < NL) ssim[t] = e;
    float s = e;
    #pragma unroll
    for (int o = 16; o > 0; o >>= 1) s += __shfl_xor_sync(0xFFFFFFFFu, s, o);
    if (lane == 0) sred[w] = s;
    __syncthreads();
    if (t == 0) { float ss = 0.f; for (int i = 0; i < 8; i++) ss += sred[i]; sred[0] = ss; }
    __syncthreads();
    const float inv = 1.0f / sred[0];

    // pass 2: Q[d] = sum_l attn_l * seqs[l][d]
    const int d = t & 63, gq = t >> 6;
    float acc = 0.f;
    for (int l = gq; l < NL; l += 4)
        acc += ssim[l] * __bfloat162float(sseq[l][d]);
    sq[gq][d] = acc;
    __syncthreads();
    if (t < ND) {
        float q = (sq[0][t] + sq[1][t] + sq[2][t] + sq[3][t]) * inv;
        g_Q[b * ND + t] = __float2bfloat16(q * 1.44269504088896340736f);  // *log2(e)
        int pid = pred[b];
        sq[0][t] = q * item_emb[(size_t)pid * ND + t];
    }
    __syncthreads();
    if (t == 0) {
        float lp = 0.f;
        for (int i = 0; i < ND; i++) lp += sq[0][i];
        g_LP[b] = lp;
    }
}

// ---------------- K2: fused GEMM (mma.sync bf16) + exp2-sum epilogue ----------------
// Grid (GX, 8). CTA (x, y): M rows [y*128, y*128+128), vocab chunks x, x+GX, ...
// Each chunk: 64 vocab rows of E in smem (row stride 144 B, conflict-free frag loads).
// Warp w owns M rows [y*128+w*16, +16). A-frags (Q) live in regs for the whole kernel.
// Deterministic: each x-CTA writes its partial sum to g_Spart[x][row]; K3 reduces.
__global__ __launch_bounds__(256) void gemm_kernel() {
    __shared__ __align__(16) char sE[2][64 * 144];   // double-buffered E chunk (18.4 KB)
    const int t = threadIdx.x, w = t >> 5, lane = t & 31;
    const int g = lane >> 2, tg = lane & 3;
    const int m0 = blockIdx.y * 128 + w * 16;
    const uint32_t sb0 = smem_u32(sE[0]);
    const uint32_t sb1 = smem_u32(sE[1]);

    // A fragments: Q[m0..m0+16) x k[0..64), held in registers across all chunks
    uint32_t a[4][4];
    #pragma unroll
    for (int s = 0; s < 4; s++) {
        int col = s * 16 + tg * 2;
        a[s][0] = *reinterpret_cast<const uint32_t*>(g_Q + (m0 + g) * ND + col);
        a[s][1] = *reinterpret_cast<const uint32_t*>(g_Q + (m0 + g + 8) * ND + col);
        a[s][2] = *reinterpret_cast<const uint32_t*>(g_Q + (m0 + g) * ND + col + 8);
        a[s][3] = *reinterpret_cast<const uint32_t*>(g_Q + (m0 + g + 8) * ND + col + 8);
    }

    float sum0 = 0.f, sum1 = 0.f;

    // prefetch first chunk into buffer 0
    int c = blockIdx.x;
    {
        int idx = t;
        #pragma unroll
        for (int it = 0; it < 2; it++, idx += 256) {
            int r = idx >> 3, u = idx & 7;
            cp_async16(sb0 + r * 144 + u * 16,
                       reinterpret_cast<const char*>(g_E) + (size_t)c * 8192 + idx * 16);
        }
        asm volatile("cp.async.commit_group;" ::: "memory");
    }

    int ph = 0;
    for (; c < NCH; c += GX) {
        int cn = c + GX;
        if (cn < NCH) {
            uint32_t dstb = (ph ? sb0 : sb1);
            int idx = t;
            #pragma unroll
            for (int it = 0; it < 2; it++, idx += 256) {
                int r = idx >> 3, u = idx & 7;
                cp_async16(dstb + r * 144 + u * 16,
                           reinterpret_cast<const char*>(g_E) + (size_t)cn * 8192 + idx * 16);
            }
        }
        asm volatile("cp.async.commit_group;" ::: "memory");
        asm volatile("cp.async.wait_group 1;" ::: "memory");
        __syncthreads();

        const char* buf = sE[ph];
        #pragma unroll
        for (int nt = 0; nt < 8; nt++) {
            float c0 = 0.f, c1 = 0.f, c2 = 0.f, c3 = 0.f;
            const char* bp = buf + (nt * 8 + g) * 144 + tg * 4;
            #pragma unroll
            for (int s = 0; s < 4; s++) {
                uint32_t b0 = *reinterpret_cast<const uint32_t*>(bp + s * 32);
                uint32_t b1 = *reinterpret_cast<const uint32_t*>(bp + s * 32 + 16);
                asm volatile(
                    "mma.sync.aligned.m16n8k16.row.col.f32.bf16.bf16.f32 "
                    "{%0,%1,%2,%3}, {%4,%5,%6,%7}, {%8,%9}, {%0,%1,%2,%3};"
                    : "+f"(c0), "+f"(c1), "+f"(c2), "+f"(c3)
                    : "r"(a[s][0]), "r"(a[s][1]), "r"(a[s][2]), "r"(a[s][3]),
                      "r"(b0), "r"(b1));
            }
            sum0 += ex2f(c0) + ex2f(c1);   // rows m0+g
            sum1 += ex2f(c2) + ex2f(c3);   // rows m0+g+8
        }
        __syncthreads();   // all reads of buf[ph] done before it is refilled next iter
        ph ^= 1;
    }

    // reduce the 4 lanes (tg) that share each M row; deterministic partial store
    sum0 += __shfl_xor_sync(0xFFFFFFFFu, sum0, 1);
    sum0 += __shfl_xor_sync(0xFFFFFFFFu, sum0, 2);
    sum1 += __shfl_xor_sync(0xFFFFFFFFu, sum1, 1);
    sum1 += __shfl_xor_sync(0xFFFFFFFFu, sum1, 2);
    if (tg == 0) {
        g_Spart[blockIdx.x][m0 + g] = sum0;
        g_Spart[blockIdx.x][m0 + g + 8] = sum1;
    }
}

// ---------------- K3: reduce partials + final gather ----------------
__global__ void final_kernel(float* __restrict__ out) {
    int i = blockIdx.x * 256 + threadIdx.x;
    if (i < NB) {
        float s = 0.f;
        #pragma unroll 4
        for (int x = 0; x < GX; x++) s += g_Spart[x][i];
        out[i] = __expf(g_LP[i]) / (s - PAD_N);
    }
}

// ---------------- launch ----------------
extern "C" void kernel_launch(void* const* d_in, const int* in_sizes, int n_in,
                              void* d_out, int out_size) {
    const int*   log_seqs = (const int*)d_in[0];
    const int*   pred     = (const int*)d_in[1];
    const float* item_emb = (const float*)d_in[2];
    const float* attn_key = (const float*)d_in[3];
    const float* pos_emb  = (const float*)d_in[4];
    float* out = (float*)d_out;

    convert_kernel<<<(NV_V * ND / 2 + 255) / 256, 256>>>(item_emb);
    q_kernel<<<NB, 256>>>(log_seqs, pred, item_emb, attn_key, pos_emb);
    gemm_kernel<<<dim3(GX, NB / 128, 1), 256>>>();
    final_kernel<<<(NB + 255) / 256, 256>>>(out);
}

// round 6
// speedup vs baseline: 1.1588x; 1.1588x over previous
#include <cuda_runtime.h>
#include <cuda_bf16.h>
#include <cstdint>

#define NV_V    100001
#define NV_VPAD 100096
#define NB      1024
#define NL      200
#define ND      64
#define NCH     1563          // ceil(100001/64); coverage 100032
#define PAD_N   31.0f         // 100032 - 100001 zero-padded cols, each contributes 2^0 = 1
#define GX      74
#define CVT_N   (NV_V * ND / 4)          // 1600016 float4s
#define CVT_B   ((CVT_N + 255) / 256)    // 6251 blocks

// ---------------- device-global scratch (no allocs allowed) ----------------
__device__ __nv_bfloat16 g_E[(size_t)NV_VPAD * ND];   // bf16 item_emb; tail rows stay zero
__device__ __nv_bfloat16 g_Q[NB * ND];                // bf16 Q, pre-scaled by log2(e)
__device__ float g_Spart[NB][GX];                     // partial denominators, row-contiguous
__device__ float g_LP[NB];                            // logit at pred[b] (fp32)

__device__ __forceinline__ uint32_t smem_u32(const void* p) {
    uint32_t a;
    asm("{ .reg .u64 t; cvta.to.shared.u64 t, %1; cvt.u32.u64 %0, t; }" : "=r"(a) : "l"(p));
    return a;
}
__device__ __forceinline__ float ex2f(float x) {
    float r; asm("ex2.approx.ftz.f32 %0, %1;" : "=f"(r) : "f"(x)); return r;
}
__device__ __forceinline__ void cp_async16(uint32_t dst, const void* src) {
    asm volatile("cp.async.cg.shared.global [%0], [%1], 16;" :: "r"(dst), "l"(src) : "memory");
}

// ---------------- K1: fused [q-pooling | fp32->bf16 convert] ----------------
// Blocks [0, NB): attention pooling for batch b = blockIdx.x.
// Blocks [NB, NB+CVT_B): convert item_emb to bf16 g_E (float4-wide).
__global__ __launch_bounds__(256) void prep_kernel(const int* __restrict__ log_seqs,
                                                   const int* __restrict__ pred,
                                                   const float* __restrict__ item_emb,
                                                   const float* __restrict__ attn_key,
                                                   const float* __restrict__ pos_emb) {
    __shared__ __nv_bfloat16 sseq[NL][ND];
    __shared__ float ssim[NL];
    __shared__ float skey[ND];
    __shared__ float sred[8];
    __shared__ float sq[4][ND];

    const int t = threadIdx.x;

    if (blockIdx.x >= NB) {
        // ---- convert branch ----
        int i = (blockIdx.x - NB) * 256 + t;
        if (i < CVT_N) {
            float4 v = reinterpret_cast<const float4*>(item_emb)[i];
            __nv_bfloat162 lo = __floats2bfloat162_rn(v.x, v.y);
            __nv_bfloat162 hi = __floats2bfloat162_rn(v.z, v.w);
            reinterpret_cast<__nv_bfloat162*>(g_E)[2 * i]     = lo;
            reinterpret_cast<__nv_bfloat162*>(g_E)[2 * i + 1] = hi;
        }
        return;
    }

    // ---- q-pooling branch ----
    const int b = blockIdx.x;
    const int w = t >> 5, lane = t & 31;
    if (t < ND) skey[t] = attn_key[t];
    __syncthreads();

    // pass 1: gather + build seqs (bf16 in smem), sim = seqs . key
    for (int l = w; l < NL; l += 8) {
        int id = log_seqs[b * NL + l];
        int d0 = lane * 2;
        float2 e = *reinterpret_cast<const float2*>(item_emb + (size_t)id * ND + d0);
        float2 p = *reinterpret_cast<const float2*>(pos_emb + l * ND + d0);
        float v0 = 0.f, v1 = 0.f;
        if (id != 0) { v0 = e.x * 8.f + p.x; v1 = e.y * 8.f + p.y; }
        sseq[l][d0]     = __float2bfloat16(v0);
        sseq[l][d0 + 1] = __float2bfloat16(v1);
        float s = v0 * skey[d0] + v1 * skey[d0 + 1];
        #pragma unroll
        for (int o = 16; o > 0; o >>= 1) s += __shfl_xor_sync(0xFFFFFFFFu, s, o);
        if (lane == 0) ssim[l] = (id != 0) ? s : -1e30f;
    }
    __syncthreads();

    // softmax over L
    float v = (t < NL) ? ssim[t] : -1e30f;
    float m = v;
    #pragma unroll
    for (int o = 16; o > 0; o >>= 1) m = fmaxf(m, __shfl_xor_sync(0xFFFFFFFFu, m, o));
    if (lane == 0) sred[w] = m;
    __syncthreads();
    if (t == 0) { float mm = sred[0]; for (int i = 1; i < 8; i++) mm = fmaxf(mm, sred[i]); sred[0] = mm; }
    __syncthreads();
    const float mx = sred[0];
    __syncthreads();
    float e = (t < NL) ? __expf(v - mx) : 0.f;
    if (t < NL) ssim[t] = e;
    float s = e;
    #pragma unroll
    for (int o = 16; o > 0; o >>= 1) s += __shfl_xor_sync(0xFFFFFFFFu, s, o);
    if (lane == 0) sred[w] = s;
    __syncthreads();
    if (t == 0) { float ss = 0.f; for (int i = 0; i < 8; i++) ss += sred[i]; sred[0] = ss; }
    __syncthreads();
    const float inv = 1.0f / sred[0];

    // pass 2: Q[d] = sum_l attn_l * seqs[l][d]
    const int d = t & 63, gq = t >> 6;
    float acc = 0.f;
    for (int l = gq; l < NL; l += 4)
        acc += ssim[l] * __bfloat162float(sseq[l][d]);
    sq[gq][d] = acc;
    __syncthreads();
    if (t < ND) {
        float q = (sq[0][t] + sq[1][t] + sq[2][t] + sq[3][t]) * inv;
        g_Q[b * ND + t] = __float2bfloat16(q * 1.44269504088896340736f);  // *log2(e)
        int pid = pred[b];
        sq[0][t] = q * item_emb[(size_t)pid * ND + t];
    }
    __syncthreads();
    if (t == 0) {
        float lp = 0.f;
        for (int i = 0; i < ND; i++) lp += sq[0][i];
        g_LP[b] = lp;
    }
}

// ---------------- K2: fused GEMM (mma.sync bf16) + exp2-sum epilogue ----------------
// Grid (GX, 8). CTA (x, y): M rows [y*128, y*128+128), vocab chunks x, x+GX, ...
// 3-stage cp.async ring (one __syncthreads per chunk). Warp w owns 16 M rows;
// A-frags (Q) live in registers for the whole kernel. Deterministic partials.
__global__ __launch_bounds__(256) void gemm_kernel() {
    __shared__ __align__(16) char sE[3][64 * 144];   // 27.6 KB ring
    const int t = threadIdx.x, w = t >> 5, lane = t & 31;
    const int g = lane >> 2, tg = lane & 3;
    const int m0 = blockIdx.y * 128 + w * 16;
    uint32_t sb[3] = { smem_u32(sE[0]), smem_u32(sE[1]), smem_u32(sE[2]) };

    // A fragments: Q[m0..m0+16) x k[0..64)
    uint32_t a[4][4];
    #pragma unroll
    for (int s = 0; s < 4; s++) {
        int col = s * 16 + tg * 2;
        a[s][0] = *reinterpret_cast<const uint32_t*>(g_Q + (m0 + g) * ND + col);
        a[s][1] = *reinterpret_cast<const uint32_t*>(g_Q + (m0 + g + 8) * ND + col);
        a[s][2] = *reinterpret_cast<const uint32_t*>(g_Q + (m0 + g) * ND + col + 8);
        a[s][3] = *reinterpret_cast<const uint32_t*>(g_Q + (m0 + g + 8) * ND + col + 8);
    }

    float sum0 = 0.f, sum1 = 0.f;
    const int r0 = t >> 3, u0 = t & 7;           // each thread: rows r0, r0+32
    const uint32_t soff = r0 * 144 + u0 * 16;

    // prefetch stages 0 and 1
    #pragma unroll
    for (int p = 0; p < 2; p++) {
        int cc = blockIdx.x + p * GX;
        if (cc < NCH) {
            const char* src = reinterpret_cast<const char*>(g_E) + (size_t)cc * 8192;
            cp_async16(sb[p] + soff, src + t * 16);
            cp_async16(sb[p] + soff + 32 * 144, src + (t + 256) * 16);
        }
        asm volatile("cp.async.commit_group;" ::: "memory");
    }

    int ph = 0;
    for (int c = blockIdx.x; c < NCH; c += GX) {
        asm volatile("cp.async.wait_group 1;" ::: "memory");   // stage ph ready
        __syncthreads();

        // refill stage (ph+2)%3 (its previous contents were consumed at iter-1;
        // the barrier above fences all readers)
        int cn = c + 2 * GX;
        int pn = ph + 2; if (pn >= 3) pn -= 3;
        if (cn < NCH) {
            const char* src = reinterpret_cast<const char*>(g_E) + (size_t)cn * 8192;
            cp_async16(sb[pn] + soff, src + t * 16);
            cp_async16(sb[pn] + soff + 32 * 144, src + (t + 256) * 16);
        }
        asm volatile("cp.async.commit_group;" ::: "memory");

        const char* buf = sE[ph];
        #pragma unroll
        for (int nt = 0; nt < 8; nt++) {
            float c0 = 0.f, c1 = 0.f, c2 = 0.f, c3 = 0.f;
            const char* bp = buf + (nt * 8 + g) * 144 + tg * 4;
            #pragma unroll
            for (int s = 0; s < 4; s++) {
                uint32_t b0 = *reinterpret_cast<const uint32_t*>(bp + s * 32);
                uint32_t b1 = *reinterpret_cast<const uint32_t*>(bp + s * 32 + 16);
                asm volatile(
                    "mma.sync.aligned.m16n8k16.row.col.f32.bf16.bf16.f32 "
                    "{%0,%1,%2,%3}, {%4,%5,%6,%7}, {%8,%9}, {%0,%1,%2,%3};"
                    : "+f"(c0), "+f"(c1), "+f"(c2), "+f"(c3)
                    : "r"(a[s][0]), "r"(a[s][1]), "r"(a[s][2]), "r"(a[s][3]),
                      "r"(b0), "r"(b1));
            }
            sum0 += ex2f(c0) + ex2f(c1);   // rows m0+g
            sum1 += ex2f(c2) + ex2f(c3);   // rows m0+g+8
        }
        ph = ph + 1 == 3 ? 0 : ph + 1;
    }

    // reduce the 4 lanes (tg) sharing each M row; deterministic partial store
    sum0 += __shfl_xor_sync(0xFFFFFFFFu, sum0, 1);
    sum0 += __shfl_xor_sync(0xFFFFFFFFu, sum0, 2);
    sum1 += __shfl_xor_sync(0xFFFFFFFFu, sum1, 1);
    sum1 += __shfl_xor_sync(0xFFFFFFFFu, sum1, 2);
    if (tg == 0) {
        g_Spart[m0 + g][blockIdx.x] = sum0;
        g_Spart[m0 + g + 8][blockIdx.x] = sum1;
    }
}

// ---------------- K3: reduce partials + final gather (warp per row) ----------------
__global__ __launch_bounds__(256) void final_kernel(float* __restrict__ out) {
    const int gw = (blockIdx.x * 256 + threadIdx.x) >> 5;   // global warp id = row
    const int lane = threadIdx.x & 31;
    if (gw < NB) {
        float s = 0.f;
        for (int x = lane; x < GX; x += 32) s += g_Spart[gw][x];
        #pragma unroll
        for (int o = 16; o > 0; o >>= 1) s += __shfl_xor_sync(0xFFFFFFFFu, s, o);
        if (lane == 0) out[gw] = __expf(g_LP[gw]) / (s - PAD_N);
    }
}

// ---------------- launch ----------------
extern "C" void kernel_launch(void* const* d_in, const int* in_sizes, int n_in,
                              void* d_out, int out_size) {
    const int*   log_seqs = (const int*)d_in[0];
    const int*   pred     = (const int*)d_in[1];
    const float* item_emb = (const float*)d_in[2];
    const float* attn_key = (const float*)d_in[3];
    const float* pos_emb  = (const float*)d_in[4];
    float* out = (float*)d_out;

    prep_kernel<<<NB + CVT_B, 256>>>(log_seqs, pred, item_emb, attn_key, pos_emb);
    gemm_kernel<<<dim3(GX, NB / 128, 1), 256>>>();
    final_kernel<<<NB * 32 / 256, 256>>>(out);
}

// round 8
// speedup vs baseline: 1.1775x; 1.0161x over previous
#include <cuda_runtime.h>
#include <cuda_bf16.h>
#include <cstdint>

#define NV_V    100001
#define NV_VPAD 100096
#define NB      1024
#define NL      200
#define ND      64
#define NCH     1563          // ceil(100001/64); coverage 100032
#define PAD_N   31.0f         // zero-padded cols each contribute 2^0 = 1
#define GX      74
#define ESTRIDE 80            // smem row stride for 64B fp8 rows (conflict-free)
#define CVT_N   (NV_V * ND / 8)          // 800008 8-byte packs
#define CVT_B   ((CVT_N + 255) / 256)    // 3126 blocks

// ---------------- device-global scratch ----------------
__device__ uint8_t g_E8[(size_t)NV_VPAD * ND];   // e4m3 item_emb; tail rows stay zero
__device__ uint8_t g_Q8[NB * ND];                // e4m3 Q, pre-scaled by log2(e)
__device__ float g_Spart[NB][GX];                // partial denominators, row-contiguous
__device__ float g_LP[NB];                       // exact logit at pred[b]

__device__ __forceinline__ uint32_t smem_u32(const void* p) {
    uint32_t a;
    asm("{ .reg .u64 t; cvta.to.shared.u64 t, %1; cvt.u32.u64 %0, t; }" : "=r"(a) : "l"(p));
    return a;
}
__device__ __forceinline__ float ex2f(float x) {
    float r; asm("ex2.approx.ftz.f32 %0, %1;" : "=f"(r) : "f"(x)); return r;
}
__device__ __forceinline__ void cp_async16(uint32_t dst, const void* src) {
    asm volatile("cp.async.cg.shared.global [%0], [%1], 16;" :: "r"(dst), "l"(src) : "memory");
}
// pack (lo, hi) floats into e4m3x2 (low byte = lo)
__device__ __forceinline__ uint16_t cvt2_e4m3(float lo, float hi) {
    uint16_t r;
    asm("cvt.rn.satfinite.e4m3x2.f32 %0, %1, %2;" : "=h"(r) : "f"(hi), "f"(lo));
    return r;
}

// ---------------- K1: fused [q-pooling | fp32 -> e4m3 convert] ----------------
__global__ __launch_bounds__(256) void prep_kernel(const int* __restrict__ log_seqs,
                                                   const int* __restrict__ pred,
                                                   const float* __restrict__ item_emb,
                                                   const float* __restrict__ attn_key,
                                                   const float* __restrict__ pos_emb) {
    __shared__ __nv_bfloat16 sseq[NL][ND + 2];   // row pad -> 132B stride, conflict-free
    __shared__ float ssim[NL];
    __shared__ float skey[ND];
    __shared__ float sred[8];
    __shared__ float sq[4][ND];
    __shared__ float sqf[ND];

    const int t = threadIdx.x;

    if (blockIdx.x >= NB) {
        // ---- convert branch: 8 floats -> 8 e4m3 bytes per thread ----
        int i = (blockIdx.x - NB) * 256 + t;
        if (i < CVT_N) {
            const float4* src = reinterpret_cast<const float4*>(item_emb) + 2 * (size_t)i;
            float4 v0 = src[0], v1 = src[1];
            uint64_t p = (uint64_t)cvt2_e4m3(v0.x, v0.y)
                       | ((uint64_t)cvt2_e4m3(v0.z, v0.w) << 16)
                       | ((uint64_t)cvt2_e4m3(v1.x, v1.y) << 32)
                       | ((uint64_t)cvt2_e4m3(v1.z, v1.w) << 48);
            reinterpret_cast<uint64_t*>(g_E8)[i] = p;
        }
        return;
    }

    // ---- q-pooling branch ----
    const int b = blockIdx.x;
    const int w = t >> 5, lane = t & 31;
    if (t < ND) skey[t] = attn_key[t];
    __syncthreads();

    // pass 1: gather only (no reductions) -> sseq
    int myid = 0;
    if (lane < 25) myid = log_seqs[b * NL + w + lane * 8];
    #pragma unroll 5
    for (int i = 0; i < 25; i++) {
        int l = w + i * 8;
        int id = __shfl_sync(0xFFFFFFFFu, myid, i);
        int d0 = lane * 2;
        float2 e = *reinterpret_cast<const float2*>(item_emb + (size_t)id * ND + d0);
        float2 p = *reinterpret_cast<const float2*>(pos_emb + l * ND + d0);
        float v0 = 0.f, v1 = 0.f;
        if (id != 0) { v0 = fmaf(e.x, 8.f, p.x); v1 = fmaf(e.y, 8.f, p.y); }
        sseq[l][d0]     = __float2bfloat16(v0);
        sseq[l][d0 + 1] = __float2bfloat16(v1);
    }
    __syncthreads();

    // sim: thread-per-row dot product from smem (conflict-free: 33-word row stride)
    if (t < NL) {
        const __nv_bfloat162* row = reinterpret_cast<const __nv_bfloat162*>(sseq[t]);
        float sim = 0.f;
        #pragma unroll
        for (int d2 = 0; d2 < 32; d2++) {
            __nv_bfloat162 sv = row[d2];
            sim = fmaf(__bfloat162float(__low2bfloat16(sv)),  skey[2 * d2],     sim);
            sim = fmaf(__bfloat162float(__high2bfloat16(sv)), skey[2 * d2 + 1], sim);
        }
        int id = log_seqs[b * NL + t];
        ssim[t] = (id != 0) ? sim : -1e30f;
    }
    __syncthreads();

    // softmax over L
    float v = (t < NL) ? ssim[t] : -1e30f;
    float m = v;
    #pragma unroll
    for (int o = 16; o > 0; o >>= 1) m = fmaxf(m, __shfl_xor_sync(0xFFFFFFFFu, m, o));
    if (lane == 0) sred[w] = m;
    __syncthreads();
    if (t == 0) { float mm = sred[0]; for (int i = 1; i < 8; i++) mm = fmaxf(mm, sred[i]); sred[0] = mm; }
    __syncthreads();
    const float mx = sred[0];
    __syncthreads();
    float e = (t < NL) ? __expf(v - mx) : 0.f;
    if (t < NL) ssim[t] = e;
    float s = e;
    #pragma unroll
    for (int o = 16; o > 0; o >>= 1) s += __shfl_xor_sync(0xFFFFFFFFu, s, o);
    if (lane == 0) sred[w] = s;
    __syncthreads();
    if (t == 0) { float ss = 0.f; for (int i = 0; i < 8; i++) ss += sred[i]; sred[0] = ss; }
    __syncthreads();
    const float inv = 1.0f / sred[0];

    // pass 2: Q[d] = sum_l attn_l * seqs[l][d]
    const int d = t & 63, gq = t >> 6;
    float acc = 0.f;
    for (int l = gq; l < NL; l += 4)
        acc += ssim[l] * __bfloat162float(sseq[l][d]);
    sq[gq][d] = acc;
    __syncthreads();
    if (t < ND) {
        float q = (sq[0][t] + sq[1][t] + sq[2][t] + sq[3][t]) * inv;
        sqf[t] = q * 1.44269504088896340736f;   // *log2(e), for fp8 Q
        int pid = pred[b];
        sq[0][t] = q * item_emb[(size_t)pid * ND + t];
    }
    __syncthreads();
    if (t < 32)   // pack Q to e4m3
        reinterpret_cast<uint16_t*>(g_Q8 + b * ND)[t] = cvt2_e4m3(sqf[2 * t], sqf[2 * t + 1]);
    if (t == 0) {
        float lp = 0.f;
        for (int i = 0; i < ND; i++) lp += sq[0][i];
        g_LP[b] = lp;
    }
}

// ---------------- K2: fused FP8 GEMM (mma.sync e4m3) + exp2-sum epilogue ----------------
// Grid (GX, 8). 3-stage cp.async ring; warp w owns 16 M rows; A-frags in regs.
__global__ __launch_bounds__(256) void gemm_kernel() {
    __shared__ __align__(16) char sE[3][64 * ESTRIDE];   // 15 KB ring
    const int t = threadIdx.x, w = t >> 5, lane = t & 31;
    const int g = lane >> 2, tg = lane & 3;
    const int m0 = blockIdx.y * 128 + w * 16;
    uint32_t sb[3] = { smem_u32(sE[0]), smem_u32(sE[1]), smem_u32(sE[2]) };

    // A fragments: Q8[m0..m0+16) x k[0..64), 2 k-groups of 32
    uint32_t a[2][4];
    #pragma unroll
    for (int kk = 0; kk < 2; kk++) {
        const uint8_t* q0 = g_Q8 + (m0 + g) * ND + kk * 32 + tg * 4;
        const uint8_t* q1 = g_Q8 + (m0 + g + 8) * ND + kk * 32 + tg * 4;
        a[kk][0] = *reinterpret_cast<const uint32_t*>(q0);
        a[kk][1] = *reinterpret_cast<const uint32_t*>(q1);
        a[kk][2] = *reinterpret_cast<const uint32_t*>(q0 + 16);
        a[kk][3] = *reinterpret_cast<const uint32_t*>(q1 + 16);
    }

    float sum0 = 0.f, sum1 = 0.f;
    const uint32_t soff = (t >> 2) * ESTRIDE + (t & 3) * 16;   // row t/4, 16B seg t%4
    const uint32_t goff = t * 16;

    // prefetch stages 0 and 1
    #pragma unroll
    for (int p = 0; p < 2; p++) {
        int cc = blockIdx.x + p * GX;
        if (cc < NCH)
            cp_async16(sb[p] + soff, g_E8 + (size_t)cc * 4096 + goff);
        asm volatile("cp.async.commit_group;" ::: "memory");
    }

    int ph = 0;
    for (int c = blockIdx.x; c < NCH; c += GX) {
        asm volatile("cp.async.wait_group 1;" ::: "memory");
        __syncthreads();

        int cn = c + 2 * GX;
        int pn = ph + 2; if (pn >= 3) pn -= 3;
        if (cn < NCH)
            cp_async16(sb[pn] + soff, g_E8 + (size_t)cn * 4096 + goff);
        asm volatile("cp.async.commit_group;" ::: "memory");

        const char* buf = sE[ph];
        #pragma unroll
        for (int nt = 0; nt < 8; nt++) {
            float c0 = 0.f, c1 = 0.f, c2 = 0.f, c3 = 0.f;
            const char* bp = buf + (nt * 8 + g) * ESTRIDE + tg * 4;
            #pragma unroll
            for (int kk = 0; kk < 2; kk++) {
                uint32_t b0 = *reinterpret_cast<const uint32_t*>(bp + kk * 32);
                uint32_t b1 = *reinterpret_cast<const uint32_t*>(bp + kk * 32 + 16);
                asm volatile(
                    "mma.sync.aligned.m16n8k32.row.col.f32.e4m3.e4m3.f32 "
                    "{%0,%1,%2,%3}, {%4,%5,%6,%7}, {%8,%9}, {%0,%1,%2,%3};"
                    : "+f"(c0), "+f"(c1), "+f"(c2), "+f"(c3)
                    : "r"(a[kk][0]), "r"(a[kk][1]), "r"(a[kk][2]), "r"(a[kk][3]),
                      "r"(b0), "r"(b1));
            }
            sum0 += ex2f(c0) + ex2f(c1);   // rows m0+g
            sum1 += ex2f(c2) + ex2f(c3);   // rows m0+g+8
        }
        ph = ph + 1 == 3 ? 0 : ph + 1;
    }

    sum0 += __shfl_xor_sync(0xFFFFFFFFu, sum0, 1);
    sum0 += __shfl_xor_sync(0xFFFFFFFFu, sum0, 2);
    sum1 += __shfl_xor_sync(0xFFFFFFFFu, sum1, 1);
    sum1 += __shfl_xor_sync(0xFFFFFFFFu, sum1, 2);
    if (tg == 0) {
        g_Spart[m0 + g][blockIdx.x] = sum0;
        g_Spart[m0 + g + 8][blockIdx.x] = sum1;
    }
}

// ---------------- K3: reduce partials + final gather (warp per row) ----------------
__global__ __launch_bounds__(256) void final_kernel(float* __restrict__ out) {
    const int gw = (blockIdx.x * 256 + threadIdx.x) >> 5;
    const int lane = threadIdx.x & 31;
    if (gw < NB) {
        float s = 0.f;
        for (int x = lane; x < GX; x += 32) s += g_Spart[gw][x];
        #pragma unroll
        for (int o = 16; o > 0; o >>= 1) s += __shfl_xor_sync(0xFFFFFFFFu, s, o);
        if (lane == 0) out[gw] = __expf(g_LP[gw]) / (s - PAD_N);
    }
}

// ---------------- launch ----------------
extern "C" void kernel_launch(void* const* d_in, const int* in_sizes, int n_in,
                              void* d_out, int out_size) {
    const int*   log_seqs = (const int*)d_in[0];
    const int*   pred     = (const int*)d_in[1];
    const float* item_emb = (const float*)d_in[2];
    const float* attn_key = (const float*)d_in[3];
    const float* pos_emb  = (const float*)d_in[4];
    float* out = (float*)d_out;

    prep_kernel<<<NB + CVT_B, 256>>>(log_seqs, pred, item_emb, attn_key, pos_emb);
    gemm_kernel<<<dim3(GX, NB / 128, 1), 256>>>();
    final_kernel<<<NB * 32 / 256, 256>>>(out);
}